// round 15
// baseline (speedup 1.0000x reference)
#include <cuda_runtime.h>
#include <cuda_fp16.h>
#include <math_constants.h>
#include <cstdint>

typedef unsigned int u32;

#define NGRAPH 1024
#define D      256
#define NITERS 6
#define NSPLIT 4
#define MAXN   400000

// ---------------- device scratch ----------------
__device__ __align__(16) float g_h[NGRAPH * D];
__device__ __align__(16) float g_read[NGRAPH * D];
__device__ __align__(16) float g_c[2][NGRAPH * D];            // ping-pong
__device__ __align__(16) float g_gates[NGRAPH * 4 * D];
__device__ __align__(16) __half g_x16[NGRAPH * 2 * D];        // [1024][512] = [h | read] fp16
__device__ __align__(16) __half g_W16[4 * D * 2 * D];         // [1024][512] = [Wc | Wr] fp16
__device__ __align__(16) float g_pm[NGRAPH * NSPLIT];
__device__ __align__(16) float g_ps[NGRAPH * NSPLIT];
__device__ __align__(16) float g_pr[NGRAPH * NSPLIT * D];
__device__ __align__(16) __half g_feat16[(size_t)MAXN * D];   // fp16 feat copy
__device__ int g_segoff[NGRAPH + 1];

// ---------------- helpers ----------------
__device__ __forceinline__ u32 smem_u32(const void* p) {
    return (u32)__cvta_generic_to_shared(p);
}

__device__ __forceinline__ void ldsm4(u32* r, u32 addr) {
    asm volatile("ldmatrix.sync.aligned.m8n8.x4.shared.b16 {%0,%1,%2,%3}, [%4];"
        : "=r"(r[0]), "=r"(r[1]), "=r"(r[2]), "=r"(r[3]) : "r"(addr));
}

__device__ __forceinline__ void mma16816(float* c, const u32* a, u32 b0, u32 b1) {
    asm volatile(
        "mma.sync.aligned.m16n8k16.row.col.f32.f16.f16.f32 "
        "{%0,%1,%2,%3}, {%4,%5,%6,%7}, {%8,%9}, {%0,%1,%2,%3};"
        : "+f"(c[0]), "+f"(c[1]), "+f"(c[2]), "+f"(c[3])
        : "r"(a[0]), "r"(a[1]), "r"(a[2]), "r"(a[3]), "r"(b0), "r"(b1));
}

__device__ __forceinline__ void unpack8(uint4 v, float* f) {
    float2 t0 = __half22float2(*(__half2*)&v.x);
    float2 t1 = __half22float2(*(__half2*)&v.y);
    float2 t2 = __half22float2(*(__half2*)&v.z);
    float2 t3 = __half22float2(*(__half2*)&v.w);
    f[0] = t0.x; f[1] = t0.y; f[2] = t1.x; f[3] = t1.y;
    f[4] = t2.x; f[5] = t2.y; f[6] = t3.x; f[7] = t3.y;
}

// ---------------- segment offsets ----------------
__global__ void seg_offsets_kernel(const int* __restrict__ seg, int N) {
    int b = blockIdx.x * blockDim.x + threadIdx.x;
    if (b > NGRAPH) return;
    int lo = 0, hi = N;
    while (lo < hi) {
        int mid = (lo + hi) >> 1;
        if (seg[mid] < b) lo = mid + 1; else hi = mid;
    }
    g_segoff[b] = lo;
}

// W16[n][k] = W_ih[n][k] + (k < 256 ? W_hh[n][k] : 0), fp16
__global__ void prep_w16_kernel(const float* __restrict__ W_ih,
                                const float* __restrict__ W_hh) {
    int i = blockIdx.x * blockDim.x + threadIdx.x;
    if (i >= 4 * D * 2 * D) return;
    int n = i >> 9;
    int k = i & 511;
    float v = W_ih[(size_t)n * 2 * D + k];
    if (k < D) v += W_hh[(size_t)n * D + k];
    g_W16[i] = __float2half(v);
}

// ---------------- tensor-core gates GEMM ----------------
// gates[1024,1024] = X16[1024,512] @ W16[1024,512]^T + (b1 + b2)
// BM=64, BN=128, BK=32, 256 threads (8 warps: 2x4), grid (8,16) = 128 blocks.
__global__ void __launch_bounds__(256)
gemm_gates_mma_kernel(const float* __restrict__ b1, const float* __restrict__ b2)
{
    const int PAD = 40;     // halves per padded row (80B stride, conflict-free)
    __shared__ __half As[2][64][PAD];
    __shared__ __half Bs[2][128][PAD];

    int tid = threadIdx.x;
    int warp = tid >> 5;
    int lane = tid & 31;
    int wm = warp >> 2;       // 0..1
    int wn = warp & 3;        // 0..3
    int row0 = blockIdx.y * 64;
    int col0 = blockIdx.x * 128;

    float acc[2][4][4];
#pragma unroll
    for (int i = 0; i < 2; i++) {
#pragma unroll
        for (int j = 0; j < 4; j++) {
#pragma unroll
            for (int k = 0; k < 4; k++) { acc[i][j][k] = 0.f; }
        }
    }

    int arow = tid >> 2;
    int acol = (tid & 3) * 8;

    int a_r = lane & 15;
    int a_c = (lane >> 4) * 8;
    int b_rr = lane & 7;
    int b_sel = lane >> 3;
    int b_rowoff = (b_sel >> 1) * 8 + b_rr;
    int b_coloff = (b_sel & 1) * 8;

    uint4 va, vb0, vb1;
    va  = *(const uint4*)(g_x16 + (size_t)(row0 + arow) * 512 + acol);
    vb0 = *(const uint4*)(g_W16 + (size_t)(col0 + arow) * 512 + acol);
    vb1 = *(const uint4*)(g_W16 + (size_t)(col0 + arow + 64) * 512 + acol);
    *(uint4*)&As[0][arow][acol] = va;
    *(uint4*)&Bs[0][arow][acol] = vb0;
    *(uint4*)&Bs[0][arow + 64][acol] = vb1;
    __syncthreads();

    for (int t = 0; t < 16; t++) {
        if (t + 1 < 16) {
            int kk = (t + 1) * 32 + acol;
            va  = *(const uint4*)(g_x16 + (size_t)(row0 + arow) * 512 + kk);
            vb0 = *(const uint4*)(g_W16 + (size_t)(col0 + arow) * 512 + kk);
            vb1 = *(const uint4*)(g_W16 + (size_t)(col0 + arow + 64) * 512 + kk);
        }
        int cur = t & 1;
#pragma unroll
        for (int ks = 0; ks < 2; ks++) {
            u32 afrag[2][4];
            u32 bfrag[2][4];
#pragma unroll
            for (int mt = 0; mt < 2; mt++) {
                u32 addr = smem_u32(&As[cur][wm * 32 + mt * 16 + a_r][ks * 16 + a_c]);
                ldsm4(afrag[mt], addr);
            }
#pragma unroll
            for (int g = 0; g < 2; g++) {
                u32 addr = smem_u32(&Bs[cur][wn * 32 + g * 16 + b_rowoff][ks * 16 + b_coloff]);
                ldsm4(bfrag[g], addr);
            }
#pragma unroll
            for (int mt = 0; mt < 2; mt++) {
#pragma unroll
                for (int g = 0; g < 2; g++) {
                    mma16816(acc[mt][g * 2 + 0], afrag[mt], bfrag[g][0], bfrag[g][1]);
                    mma16816(acc[mt][g * 2 + 1], afrag[mt], bfrag[g][2], bfrag[g][3]);
                }
            }
        }
        if (t + 1 < 16) {
            *(uint4*)&As[cur ^ 1][arow][acol] = va;
            *(uint4*)&Bs[cur ^ 1][arow][acol] = vb0;
            *(uint4*)&Bs[cur ^ 1][arow + 64][acol] = vb1;
        }
        __syncthreads();
    }

    int trow = lane >> 2;
    int tcol = (lane & 3) * 2;
#pragma unroll
    for (int mt = 0; mt < 2; mt++) {
#pragma unroll
        for (int nt = 0; nt < 4; nt++) {
            int col = col0 + wn * 32 + nt * 8 + tcol;
            float bb0 = b1[col] + b2[col];
            float bb1 = b1[col + 1] + b2[col + 1];
            int r0 = row0 + wm * 32 + mt * 16 + trow;
            float2* p0 = (float2*)(g_gates + (size_t)r0 * 4 * D + col);
            float2* p1 = (float2*)(g_gates + (size_t)(r0 + 8) * 4 * D + col);
            *p0 = make_float2(acc[mt][nt][0] + bb0, acc[mt][nt][1] + bb1);
            *p1 = make_float2(acc[mt][nt][2] + bb0, acc[mt][nt][3] + bb1);
        }
    }
}

// ---------------- fp32 fc GEMM (runs once) ----------------
__global__ void __launch_bounds__(256)
gemm_fc_kernel(const float* __restrict__ fc_w, const float* __restrict__ fc_b,
               float* __restrict__ out)
{
    const int BK = 16, T = 32;
    __shared__ float As[2][BK][64];
    __shared__ float Bs[2][BK][64];

    int tid = threadIdx.x;
    int tx = tid & 15;
    int ty = tid >> 4;
    int row0 = blockIdx.y * 64;
    int col0 = blockIdx.x * 64;
    int lr = tid >> 2;
    int lc = (tid & 3) * 4;

    float acc[4][4];
#pragma unroll
    for (int i = 0; i < 4; i++) {
#pragma unroll
        for (int j = 0; j < 4; j++) { acc[i][j] = 0.f; }
    }

    float4 av, bv;
    av = *(const float4*)(g_h + (size_t)(row0 + lr) * D + lc);
    bv = *(const float4*)(fc_w + (size_t)(col0 + lr) * 2 * D + lc);
    As[0][lc + 0][lr] = av.x; As[0][lc + 1][lr] = av.y;
    As[0][lc + 2][lr] = av.z; As[0][lc + 3][lr] = av.w;
    Bs[0][lc + 0][lr] = bv.x; Bs[0][lc + 1][lr] = bv.y;
    Bs[0][lc + 2][lr] = bv.z; Bs[0][lc + 3][lr] = bv.w;
    __syncthreads();

    for (int t = 0; t < T; t++) {
        if (t + 1 < T) {
            int kk = (t + 1) * BK + lc;
            const float* A = (kk < D) ? g_h : g_read;
            int k2 = (kk < D) ? kk : kk - D;
            av = *(const float4*)(A + (size_t)(row0 + lr) * D + k2);
            bv = *(const float4*)(fc_w + (size_t)(col0 + lr) * 2 * D + kk);
        }
        int cur = t & 1;
#pragma unroll
        for (int k = 0; k < BK; k++) {
            float a[4], b[4];
#pragma unroll
            for (int i = 0; i < 4; i++) { a[i] = As[cur][k][ty * 4 + i]; }
#pragma unroll
            for (int j = 0; j < 4; j++) { b[j] = Bs[cur][k][tx * 4 + j]; }
#pragma unroll
            for (int i = 0; i < 4; i++) {
#pragma unroll
                for (int j = 0; j < 4; j++) { acc[i][j] += a[i] * b[j]; }
            }
        }
        if (t + 1 < T) {
            int nb = cur ^ 1;
            As[nb][lc + 0][lr] = av.x; As[nb][lc + 1][lr] = av.y;
            As[nb][lc + 2][lr] = av.z; As[nb][lc + 3][lr] = av.w;
            Bs[nb][lc + 0][lr] = bv.x; Bs[nb][lc + 1][lr] = bv.y;
            Bs[nb][lc + 2][lr] = bv.z; Bs[nb][lc + 3][lr] = bv.w;
        }
        __syncthreads();
    }

#pragma unroll
    for (int j = 0; j < 4; j++) {
        int col = col0 + tx * 4 + j;
        float bias = fc_b[col];
#pragma unroll
        for (int i = 0; i < 4; i++) {
            int row = row0 + ty * 4 + i;
            out[(size_t)row * D + col] = acc[i][j] + bias;
        }
    }
}

// ---------------- LSTM-elementwise helpers ----------------
__device__ __forceinline__ void lstm_elem(int b, int parity, float* q_sm) {
    const float* g = g_gates + (size_t)b * 4 * D;
    int d = threadIdx.x;
    float gi = g[d];
    float gf = g[D + d];
    float gg = g[2 * D + d];
    float go = g[3 * D + d];
    float si = 1.f / (1.f + __expf(-gi));
    float so = 1.f / (1.f + __expf(-go));
    float sf = 1.f / (1.f + __expf(-gf));
    float c = sf * g_c[parity][(size_t)b * D + d] + si * tanhf(gg);
    float h = so * tanhf(c);
    g_c[parity ^ 1][(size_t)b * D + d] = c;
    g_h[(size_t)b * D + d] = h;                       // fp32 (fc GEMM)
    g_x16[(size_t)b * 2 * D + d] = __float2half(h);   // fp16 (gates GEMM)
    q_sm[d] = h;
}

// Iter-0 path: gates = b1 + b2 (all GEMM inputs are zero), c_prev = 0.
__device__ __forceinline__ void lstm_elem_bias(int b, const float* b1,
                                               const float* b2, float* q_sm) {
    int d = threadIdx.x;
    float gi = b1[d] + b2[d];
    float gg = b1[2 * D + d] + b2[2 * D + d];
    float go = b1[3 * D + d] + b2[3 * D + d];
    float si = 1.f / (1.f + __expf(-gi));
    float so = 1.f / (1.f + __expf(-go));
    float c = si * tanhf(gg);                         // sf * 0 + si*tanh(g)
    float h = so * tanhf(c);
    g_c[1][(size_t)b * D + d] = c;                    // iter 0 writes parity 0^1 = 1
    g_h[(size_t)b * D + d] = h;
    g_x16[(size_t)b * 2 * D + d] = __float2half(h);
    q_sm[d] = h;
}

// ---------------- iter-0: fp32 attention + fp16 conversion write ----------------
__global__ void __launch_bounds__(256)
attn_phase1_f32_kernel(const float* __restrict__ feat,
                       const float* __restrict__ b1, const float* __restrict__ b2)
{
    int u = blockIdx.x;
    int b = u >> 2;
    int sp = u & 3;
    int tid = threadIdx.x;
    int w = tid >> 5;
    int lane = tid & 31;

    __shared__ float q_sm[D];
    lstm_elem_bias(b, b1, b2, q_sm);
    __syncthreads();

    int start = g_segoff[b];
    int end = g_segoff[b + 1];

    float4 qa = *(const float4*)(q_sm + lane * 4);
    float4 qb = *(const float4*)(q_sm + 128 + lane * 4);

    float m = -CUDART_INF_F, s = 0.f;
    float4 ra = make_float4(0.f, 0.f, 0.f, 0.f);
    float4 rb = make_float4(0.f, 0.f, 0.f, 0.f);

    for (int n = start + sp * 8 + w; n < end; n += 32) {
        const float4* fp = (const float4*)(feat + (size_t)n * D);
        float4 fa = fp[lane];
        float4 fb = fp[32 + lane];

        __half* row16 = g_feat16 + (size_t)n * D;
        ((__half2*)row16)[lane * 2 + 0] = __float22half2_rn(make_float2(fa.x, fa.y));
        ((__half2*)row16)[lane * 2 + 1] = __float22half2_rn(make_float2(fa.z, fa.w));
        ((__half2*)(row16 + 128))[lane * 2 + 0] = __float22half2_rn(make_float2(fb.x, fb.y));
        ((__half2*)(row16 + 128))[lane * 2 + 1] = __float22half2_rn(make_float2(fb.z, fb.w));

        float p = fa.x * qa.x + fa.y * qa.y + fa.z * qa.z + fa.w * qa.w
                + fb.x * qb.x + fb.y * qb.y + fb.z * qb.z + fb.w * qb.w;
#pragma unroll
        for (int o = 16; o; o >>= 1) { p += __shfl_xor_sync(0xffffffffu, p, o); }

        float wgt;
        if (p > m) {
            float sc = __expf(m - p);   // first node: exp(-inf) = +0
            s *= sc;
            ra.x *= sc; ra.y *= sc; ra.z *= sc; ra.w *= sc;
            rb.x *= sc; rb.y *= sc; rb.z *= sc; rb.w *= sc;
            m = p;
            wgt = 1.f;
        } else {
            wgt = __expf(p - m);
        }
        s += wgt;
        ra.x += wgt * fa.x; ra.y += wgt * fa.y; ra.z += wgt * fa.z; ra.w += wgt * fa.w;
        rb.x += wgt * fb.x; rb.y += wgt * fb.y; rb.z += wgt * fb.z; rb.w += wgt * fb.w;
    }

    __shared__ float sm_m[8];
    __shared__ float sm_s[8];
    __shared__ float4 sm_ra[8][32];
    __shared__ float4 sm_rb[8][32];
    if (lane == 0) { sm_m[w] = m; sm_s[w] = s; }
    sm_ra[w][lane] = ra;
    sm_rb[w][lane] = rb;
    __syncthreads();

    int d = tid;
    float M = -CUDART_INF_F;
#pragma unroll
    for (int i = 0; i < 8; i++) { M = fmaxf(M, sm_m[i]); }

    float S = 0.f, R = 0.f;
    if (M > -CUDART_INF_F) {
        const float* base;
        if (d < 128) { base = ((const float*)sm_ra) + d; }
        else         { base = ((const float*)sm_rb) + (d - 128); }
#pragma unroll
        for (int i = 0; i < 8; i++) {
            float sc = __expf(sm_m[i] - M);
            S += sm_s[i] * sc;
            R += base[i * 128] * sc;
        }
    }
    g_pr[(size_t)u * D + d] = R;
    if (tid == 0) { g_pm[u] = M; g_ps[u] = S; }
}

// ---------------- iters 1..5: fp16 attention, 4-node unroll ----------------
__global__ void __launch_bounds__(256)
attn_phase1_f16_kernel(int parity)
{
    int u = blockIdx.x;
    int b = u >> 2;
    int sp = u & 3;
    int tid = threadIdx.x;
    int w = tid >> 5;
    int lane = tid & 31;

    __shared__ float q_sm[D];
    lstm_elem(b, parity, q_sm);
    __syncthreads();

    int start = g_segoff[b];
    int end = g_segoff[b + 1];

    float qv[8];
#pragma unroll
    for (int i = 0; i < 8; i++) { qv[i] = q_sm[lane * 8 + i]; }

    float m = -CUDART_INF_F, s = 0.f;
    float r[8];
#pragma unroll
    for (int i = 0; i < 8; i++) { r[i] = 0.f; }

    int n = start + sp * 8 + w;
    for (; n + 96 < end; n += 128) {
        uint4 v0 = ((const uint4*)(g_feat16 + (size_t)n * D))[lane];
        uint4 v1 = ((const uint4*)(g_feat16 + (size_t)(n + 32) * D))[lane];
        uint4 v2 = ((const uint4*)(g_feat16 + (size_t)(n + 64) * D))[lane];
        uint4 v3 = ((const uint4*)(g_feat16 + (size_t)(n + 96) * D))[lane];
        float f0[8], f1[8], f2[8], f3[8];
        unpack8(v0, f0);
        unpack8(v1, f1);
        unpack8(v2, f2);
        unpack8(v3, f3);

        float p0 = 0.f, p1 = 0.f, p2 = 0.f, p3 = 0.f;
#pragma unroll
        for (int i = 0; i < 8; i++) {
            p0 += f0[i] * qv[i]; p1 += f1[i] * qv[i];
            p2 += f2[i] * qv[i]; p3 += f3[i] * qv[i];
        }
#pragma unroll
        for (int o = 16; o; o >>= 1) {
            p0 += __shfl_xor_sync(0xffffffffu, p0, o);
            p1 += __shfl_xor_sync(0xffffffffu, p1, o);
            p2 += __shfl_xor_sync(0xffffffffu, p2, o);
            p3 += __shfl_xor_sync(0xffffffffu, p3, o);
        }

        float pmax = fmaxf(fmaxf(p0, p1), fmaxf(p2, p3));
        if (pmax > m) {
            float sc = __expf(m - pmax);   // first group: exp(-inf) = +0
            s *= sc;
#pragma unroll
            for (int i = 0; i < 8; i++) { r[i] *= sc; }
            m = pmax;
        }
        float w0 = __expf(p0 - m);
        float w1 = __expf(p1 - m);
        float w2 = __expf(p2 - m);
        float w3 = __expf(p3 - m);
        s += w0 + w1 + w2 + w3;
#pragma unroll
        for (int i = 0; i < 8; i++) {
            r[i] += (w0 * f0[i] + w1 * f1[i]) + (w2 * f2[i] + w3 * f3[i]);
        }
    }
    for (; n < end; n += 32) {
        uint4 v0 = ((const uint4*)(g_feat16 + (size_t)n * D))[lane];
        float f0[8];
        unpack8(v0, f0);
        float p = 0.f;
#pragma unroll
        for (int i = 0; i < 8; i++) { p += f0[i] * qv[i]; }
#pragma unroll
        for (int o = 16; o; o >>= 1) { p += __shfl_xor_sync(0xffffffffu, p, o); }
        if (p > m) {
            float sc = __expf(m - p);
            s *= sc;
#pragma unroll
            for (int i = 0; i < 8; i++) { r[i] *= sc; }
            m = p;
        }
        float w0 = __expf(p - m);
        s += w0;
#pragma unroll
        for (int i = 0; i < 8; i++) { r[i] += w0 * f0[i]; }
    }

    __shared__ float sm_m[8];
    __shared__ float sm_s[8];
    __shared__ float sm_r[8][D];
    if (lane == 0) { sm_m[w] = m; sm_s[w] = s; }
    *(float4*)&sm_r[w][lane * 8 + 0] = make_float4(r[0], r[1], r[2], r[3]);
    *(float4*)&sm_r[w][lane * 8 + 4] = make_float4(r[4], r[5], r[6], r[7]);
    __syncthreads();

    int d = tid;
    float M = -CUDART_INF_F;
#pragma unroll
    for (int i = 0; i < 8; i++) { M = fmaxf(M, sm_m[i]); }

    float S = 0.f, R = 0.f;
    if (M > -CUDART_INF_F) {
#pragma unroll
        for (int i = 0; i < 8; i++) {
            float sc = __expf(sm_m[i] - M);
            S += sm_s[i] * sc;
            R += sm_r[i][d] * sc;
        }
    }
    g_pr[(size_t)u * D + d] = R;
    if (tid == 0) { g_pm[u] = M; g_ps[u] = S; }
}

// ---------------- merge NSPLIT partials per graph ----------------
__global__ void __launch_bounds__(256)
attn_merge_kernel()
{
    int b = blockIdx.x;
    int d = threadIdx.x;

    float pm[NSPLIT];
#pragma unroll
    for (int i = 0; i < NSPLIT; i++) { pm[i] = g_pm[b * NSPLIT + i]; }

    float M = -CUDART_INF_F;
#pragma unroll
    for (int i = 0; i < NSPLIT; i++) { M = fmaxf(M, pm[i]); }

    float out = 0.f;
    if (M > -CUDART_INF_F) {
        float S = 0.f, R = 0.f;
#pragma unroll
        for (int i = 0; i < NSPLIT; i++) {
            float e = __expf(pm[i] - M);
            S += g_ps[b * NSPLIT + i] * e;
            R += g_pr[(size_t)(b * NSPLIT + i) * D + d] * e;
        }
        if (S > 0.f) { out = R / S; }
    }
    g_read[(size_t)b * D + d] = out;                          // fp32 (fc GEMM)
    g_x16[(size_t)b * 2 * D + D + d] = __float2half(out);     // fp16 (gates GEMM)
}

// ---------------- launch ----------------
extern "C" void kernel_launch(void* const* d_in, const int* in_sizes, int n_in,
                              void* d_out, int out_size)
{
    const float* feat = 0;
    const float* W_ih = 0;
    const float* W_hh = 0;
    const float* fc_w = 0;
    const float* fc_b = 0;
    const float* b_1 = 0;
    const float* b_2 = 0;
    const int* seg = 0;

    int fi = 0;
    long long best = -1;
    for (int i = 0; i < n_in; i++) {
        if ((long long)in_sizes[i] > best) { best = in_sizes[i]; fi = i; }
    }
    feat = (const float*)d_in[fi];
    int N = in_sizes[fi] / D;

    for (int i = 0; i < n_in; i++) {
        if (i == fi) continue;
        int s = in_sizes[i];
        if      (s == 4 * D * 2 * D) { W_ih = (const float*)d_in[i]; }
        else if (s == 4 * D * D)     { W_hh = (const float*)d_in[i]; }
        else if (s == D * 2 * D)     { fc_w = (const float*)d_in[i]; }
        else if (s == 4 * D)         { if (!b_1) { b_1 = (const float*)d_in[i]; }
                                       else      { b_2 = (const float*)d_in[i]; } }
        else if (s == D)             { fc_b = (const float*)d_in[i]; }
        else if (s == N)             { seg  = (const int*)d_in[i]; }
    }
    float* out = (float*)d_out;

    seg_offsets_kernel<<<(NGRAPH + 1 + 255) / 256, 256>>>(seg, N);
    prep_w16_kernel<<<(4 * D * 2 * D + 255) / 256, 256>>>(W_ih, W_hh);

    dim3 gGates(1024 / 128, 1024 / 64);   // (8, 16) = 128 blocks
    dim3 gFc(D / 64, NGRAPH / 64);        // (4, 16)

    for (int it = 0; it < NITERS; it++) {
        if (it == 0) {
            attn_phase1_f32_kernel<<<NGRAPH * NSPLIT, 256>>>(feat, b_1, b_2);
        } else {
            gemm_gates_mma_kernel<<<gGates, 256>>>(b_1, b_2);
            attn_phase1_f16_kernel<<<NGRAPH * NSPLIT, 256>>>(it & 1);
        }
        attn_merge_kernel<<<NGRAPH, 256>>>();
    }
    gemm_fc_kernel<<<gFc, 256>>>(fc_w, fc_b, out);
}

// round 16
// speedup vs baseline: 1.0626x; 1.0626x over previous
#include <cuda_runtime.h>
#include <cuda_fp16.h>
#include <math_constants.h>
#include <cstdint>

typedef unsigned int u32;

#define NGRAPH 1024
#define D      256
#define NITERS 6
#define NSPLIT 4
#define MAXN   400000

// ---------------- device scratch ----------------
__device__ __align__(16) float g_h[NGRAPH * D];
__device__ __align__(16) float g_read[NGRAPH * D];
__device__ __align__(16) float g_c[2][NGRAPH * D];            // ping-pong
__device__ __align__(16) float g_gates[NGRAPH * 4 * D];
__device__ __align__(16) __half g_x16[NGRAPH * 2 * D];        // [1024][512] = [h | read] fp16
__device__ __align__(16) __half g_W16[4 * D * 2 * D];         // [1024][512] = [Wc | Wr] fp16
__device__ __align__(16) float g_pm[NGRAPH * NSPLIT];
__device__ __align__(16) float g_ps[NGRAPH * NSPLIT];
__device__ __align__(16) float g_pr[NGRAPH * NSPLIT * D];
__device__ __align__(16) __half g_feat16[(size_t)MAXN * D];   // fp16 feat copy
__device__ int g_segoff[NGRAPH + 1];

// ---------------- helpers ----------------
__device__ __forceinline__ u32 smem_u32(const void* p) {
    return (u32)__cvta_generic_to_shared(p);
}

__device__ __forceinline__ void ldsm4(u32* r, u32 addr) {
    asm volatile("ldmatrix.sync.aligned.m8n8.x4.shared.b16 {%0,%1,%2,%3}, [%4];"
        : "=r"(r[0]), "=r"(r[1]), "=r"(r[2]), "=r"(r[3]) : "r"(addr));
}

__device__ __forceinline__ void mma16816(float* c, const u32* a, u32 b0, u32 b1) {
    asm volatile(
        "mma.sync.aligned.m16n8k16.row.col.f32.f16.f16.f32 "
        "{%0,%1,%2,%3}, {%4,%5,%6,%7}, {%8,%9}, {%0,%1,%2,%3};"
        : "+f"(c[0]), "+f"(c[1]), "+f"(c[2]), "+f"(c[3])
        : "r"(a[0]), "r"(a[1]), "r"(a[2]), "r"(a[3]), "r"(b0), "r"(b1));
}

__device__ __forceinline__ void unpack8(uint4 v, float* f) {
    float2 t0 = __half22float2(*(__half2*)&v.x);
    float2 t1 = __half22float2(*(__half2*)&v.y);
    float2 t2 = __half22float2(*(__half2*)&v.z);
    float2 t3 = __half22float2(*(__half2*)&v.w);
    f[0] = t0.x; f[1] = t0.y; f[2] = t1.x; f[3] = t1.y;
    f[4] = t2.x; f[5] = t2.y; f[6] = t3.x; f[7] = t3.y;
}

// ---------------- segment offsets ----------------
__global__ void seg_offsets_kernel(const int* __restrict__ seg, int N) {
    int b = blockIdx.x * blockDim.x + threadIdx.x;
    if (b > NGRAPH) return;
    int lo = 0, hi = N;
    while (lo < hi) {
        int mid = (lo + hi) >> 1;
        if (seg[mid] < b) lo = mid + 1; else hi = mid;
    }
    g_segoff[b] = lo;
}

// W16[n][k] = W_ih[n][k] + (k < 256 ? W_hh[n][k] : 0), fp16
__global__ void prep_w16_kernel(const float* __restrict__ W_ih,
                                const float* __restrict__ W_hh) {
    int i = blockIdx.x * blockDim.x + threadIdx.x;
    if (i >= 4 * D * 2 * D) return;
    int n = i >> 9;
    int k = i & 511;
    float v = W_ih[(size_t)n * 2 * D + k];
    if (k < D) v += W_hh[(size_t)n * D + k];
    g_W16[i] = __float2half(v);
}

// ---------------- tensor-core gates GEMM ----------------
// gates[1024,1024] = X16[1024,512] @ W16[1024,512]^T + (b1 + b2)
// BM=64, BN=128, BK=32, 256 threads (8 warps: 2x4), grid (8,16) = 128 blocks.
__global__ void __launch_bounds__(256)
gemm_gates_mma_kernel(const float* __restrict__ b1, const float* __restrict__ b2)
{
    const int PAD = 40;     // halves per padded row (80B stride, conflict-free)
    __shared__ __half As[2][64][PAD];
    __shared__ __half Bs[2][128][PAD];

    int tid = threadIdx.x;
    int warp = tid >> 5;
    int lane = tid & 31;
    int wm = warp >> 2;       // 0..1
    int wn = warp & 3;        // 0..3
    int row0 = blockIdx.y * 64;
    int col0 = blockIdx.x * 128;

    float acc[2][4][4];
#pragma unroll
    for (int i = 0; i < 2; i++) {
#pragma unroll
        for (int j = 0; j < 4; j++) {
#pragma unroll
            for (int k = 0; k < 4; k++) { acc[i][j][k] = 0.f; }
        }
    }

    int arow = tid >> 2;
    int acol = (tid & 3) * 8;

    int a_r = lane & 15;
    int a_c = (lane >> 4) * 8;
    int b_rr = lane & 7;
    int b_sel = lane >> 3;
    int b_rowoff = (b_sel >> 1) * 8 + b_rr;
    int b_coloff = (b_sel & 1) * 8;

    uint4 va, vb0, vb1;
    va  = *(const uint4*)(g_x16 + (size_t)(row0 + arow) * 512 + acol);
    vb0 = *(const uint4*)(g_W16 + (size_t)(col0 + arow) * 512 + acol);
    vb1 = *(const uint4*)(g_W16 + (size_t)(col0 + arow + 64) * 512 + acol);
    *(uint4*)&As[0][arow][acol] = va;
    *(uint4*)&Bs[0][arow][acol] = vb0;
    *(uint4*)&Bs[0][arow + 64][acol] = vb1;
    __syncthreads();

    for (int t = 0; t < 16; t++) {
        if (t + 1 < 16) {
            int kk = (t + 1) * 32 + acol;
            va  = *(const uint4*)(g_x16 + (size_t)(row0 + arow) * 512 + kk);
            vb0 = *(const uint4*)(g_W16 + (size_t)(col0 + arow) * 512 + kk);
            vb1 = *(const uint4*)(g_W16 + (size_t)(col0 + arow + 64) * 512 + kk);
        }
        int cur = t & 1;
#pragma unroll
        for (int ks = 0; ks < 2; ks++) {
            u32 afrag[2][4];
            u32 bfrag[2][4];
#pragma unroll
            for (int mt = 0; mt < 2; mt++) {
                u32 addr = smem_u32(&As[cur][wm * 32 + mt * 16 + a_r][ks * 16 + a_c]);
                ldsm4(afrag[mt], addr);
            }
#pragma unroll
            for (int g = 0; g < 2; g++) {
                u32 addr = smem_u32(&Bs[cur][wn * 32 + g * 16 + b_rowoff][ks * 16 + b_coloff]);
                ldsm4(bfrag[g], addr);
            }
#pragma unroll
            for (int mt = 0; mt < 2; mt++) {
#pragma unroll
                for (int g = 0; g < 2; g++) {
                    mma16816(acc[mt][g * 2 + 0], afrag[mt], bfrag[g][0], bfrag[g][1]);
                    mma16816(acc[mt][g * 2 + 1], afrag[mt], bfrag[g][2], bfrag[g][3]);
                }
            }
        }
        if (t + 1 < 16) {
            *(uint4*)&As[cur ^ 1][arow][acol] = va;
            *(uint4*)&Bs[cur ^ 1][arow][acol] = vb0;
            *(uint4*)&Bs[cur ^ 1][arow + 64][acol] = vb1;
        }
        __syncthreads();
    }

    int trow = lane >> 2;
    int tcol = (lane & 3) * 2;
#pragma unroll
    for (int mt = 0; mt < 2; mt++) {
#pragma unroll
        for (int nt = 0; nt < 4; nt++) {
            int col = col0 + wn * 32 + nt * 8 + tcol;
            float bb0 = b1[col] + b2[col];
            float bb1 = b1[col + 1] + b2[col + 1];
            int r0 = row0 + wm * 32 + mt * 16 + trow;
            float2* p0 = (float2*)(g_gates + (size_t)r0 * 4 * D + col);
            float2* p1 = (float2*)(g_gates + (size_t)(r0 + 8) * 4 * D + col);
            *p0 = make_float2(acc[mt][nt][0] + bb0, acc[mt][nt][1] + bb1);
            *p1 = make_float2(acc[mt][nt][2] + bb0, acc[mt][nt][3] + bb1);
        }
    }
}

// ---------------- fp32 fc GEMM (runs once) ----------------
__global__ void __launch_bounds__(256)
gemm_fc_kernel(const float* __restrict__ fc_w, const float* __restrict__ fc_b,
               float* __restrict__ out)
{
    const int BK = 16, T = 32;
    __shared__ float As[2][BK][64];
    __shared__ float Bs[2][BK][64];

    int tid = threadIdx.x;
    int tx = tid & 15;
    int ty = tid >> 4;
    int row0 = blockIdx.y * 64;
    int col0 = blockIdx.x * 64;
    int lr = tid >> 2;
    int lc = (tid & 3) * 4;

    float acc[4][4];
#pragma unroll
    for (int i = 0; i < 4; i++) {
#pragma unroll
        for (int j = 0; j < 4; j++) { acc[i][j] = 0.f; }
    }

    float4 av, bv;
    av = *(const float4*)(g_h + (size_t)(row0 + lr) * D + lc);
    bv = *(const float4*)(fc_w + (size_t)(col0 + lr) * 2 * D + lc);
    As[0][lc + 0][lr] = av.x; As[0][lc + 1][lr] = av.y;
    As[0][lc + 2][lr] = av.z; As[0][lc + 3][lr] = av.w;
    Bs[0][lc + 0][lr] = bv.x; Bs[0][lc + 1][lr] = bv.y;
    Bs[0][lc + 2][lr] = bv.z; Bs[0][lc + 3][lr] = bv.w;
    __syncthreads();

    for (int t = 0; t < T; t++) {
        if (t + 1 < T) {
            int kk = (t + 1) * BK + lc;
            const float* A = (kk < D) ? g_h : g_read;
            int k2 = (kk < D) ? kk : kk - D;
            av = *(const float4*)(A + (size_t)(row0 + lr) * D + k2);
            bv = *(const float4*)(fc_w + (size_t)(col0 + lr) * 2 * D + kk);
        }
        int cur = t & 1;
#pragma unroll
        for (int k = 0; k < BK; k++) {
            float a[4], b[4];
#pragma unroll
            for (int i = 0; i < 4; i++) { a[i] = As[cur][k][ty * 4 + i]; }
#pragma unroll
            for (int j = 0; j < 4; j++) { b[j] = Bs[cur][k][tx * 4 + j]; }
#pragma unroll
            for (int i = 0; i < 4; i++) {
#pragma unroll
                for (int j = 0; j < 4; j++) { acc[i][j] += a[i] * b[j]; }
            }
        }
        if (t + 1 < T) {
            int nb = cur ^ 1;
            As[nb][lc + 0][lr] = av.x; As[nb][lc + 1][lr] = av.y;
            As[nb][lc + 2][lr] = av.z; As[nb][lc + 3][lr] = av.w;
            Bs[nb][lc + 0][lr] = bv.x; Bs[nb][lc + 1][lr] = bv.y;
            Bs[nb][lc + 2][lr] = bv.z; Bs[nb][lc + 3][lr] = bv.w;
        }
        __syncthreads();
    }

#pragma unroll
    for (int j = 0; j < 4; j++) {
        int col = col0 + tx * 4 + j;
        float bias = fc_b[col];
#pragma unroll
        for (int i = 0; i < 4; i++) {
            int row = row0 + ty * 4 + i;
            out[(size_t)row * D + col] = acc[i][j] + bias;
        }
    }
}

// ---------------- LSTM-elementwise helpers ----------------
__device__ __forceinline__ void lstm_elem(int b, int parity, float* q_sm) {
    const float* g = g_gates + (size_t)b * 4 * D;
    int d = threadIdx.x;
    float gi = g[d];
    float gf = g[D + d];
    float gg = g[2 * D + d];
    float go = g[3 * D + d];
    float si = 1.f / (1.f + __expf(-gi));
    float so = 1.f / (1.f + __expf(-go));
    float sf = 1.f / (1.f + __expf(-gf));
    float c = sf * g_c[parity][(size_t)b * D + d] + si * tanhf(gg);
    float h = so * tanhf(c);
    g_c[parity ^ 1][(size_t)b * D + d] = c;
    g_h[(size_t)b * D + d] = h;                       // fp32 (fc GEMM)
    g_x16[(size_t)b * 2 * D + d] = __float2half(h);   // fp16 (gates GEMM)
    q_sm[d] = h;
}

// Iter-0 path: gates = b1 + b2 (all GEMM inputs are zero), c_prev = 0.
__device__ __forceinline__ void lstm_elem_bias(int b, const float* b1,
                                               const float* b2, float* q_sm) {
    int d = threadIdx.x;
    float gi = b1[d] + b2[d];
    float gg = b1[2 * D + d] + b2[2 * D + d];
    float go = b1[3 * D + d] + b2[3 * D + d];
    float si = 1.f / (1.f + __expf(-gi));
    float so = 1.f / (1.f + __expf(-go));
    float c = si * tanhf(gg);                         // sf * 0 + si*tanh(g)
    float h = so * tanhf(c);
    g_c[1][(size_t)b * D + d] = c;                    // iter 0 writes parity 0^1 = 1
    g_h[(size_t)b * D + d] = h;
    g_x16[(size_t)b * 2 * D + d] = __float2half(h);
    q_sm[d] = h;
}

// ---------------- iter-0: fp32 attention + fp16 conversion write ----------------
__global__ void __launch_bounds__(256)
attn_phase1_f32_kernel(const float* __restrict__ feat,
                       const float* __restrict__ b1, const float* __restrict__ b2)
{
    int u = blockIdx.x;
    int b = u >> 2;
    int sp = u & 3;
    int tid = threadIdx.x;
    int w = tid >> 5;
    int lane = tid & 31;

    __shared__ float q_sm[D];
    lstm_elem_bias(b, b1, b2, q_sm);
    __syncthreads();

    int start = g_segoff[b];
    int end = g_segoff[b + 1];

    float4 qa = *(const float4*)(q_sm + lane * 4);
    float4 qb = *(const float4*)(q_sm + 128 + lane * 4);

    float m = -CUDART_INF_F, s = 0.f;
    float4 ra = make_float4(0.f, 0.f, 0.f, 0.f);
    float4 rb = make_float4(0.f, 0.f, 0.f, 0.f);

    for (int n = start + sp * 8 + w; n < end; n += 32) {
        const float4* fp = (const float4*)(feat + (size_t)n * D);
        float4 fa = fp[lane];
        float4 fb = fp[32 + lane];

        __half* row16 = g_feat16 + (size_t)n * D;
        ((__half2*)row16)[lane * 2 + 0] = __float22half2_rn(make_float2(fa.x, fa.y));
        ((__half2*)row16)[lane * 2 + 1] = __float22half2_rn(make_float2(fa.z, fa.w));
        ((__half2*)(row16 + 128))[lane * 2 + 0] = __float22half2_rn(make_float2(fb.x, fb.y));
        ((__half2*)(row16 + 128))[lane * 2 + 1] = __float22half2_rn(make_float2(fb.z, fb.w));

        float p = fa.x * qa.x + fa.y * qa.y + fa.z * qa.z + fa.w * qa.w
                + fb.x * qb.x + fb.y * qb.y + fb.z * qb.z + fb.w * qb.w;
#pragma unroll
        for (int o = 16; o; o >>= 1) { p += __shfl_xor_sync(0xffffffffu, p, o); }

        float wgt;
        if (p > m) {
            float sc = __expf(m - p);   // first node: exp(-inf) = +0
            s *= sc;
            ra.x *= sc; ra.y *= sc; ra.z *= sc; ra.w *= sc;
            rb.x *= sc; rb.y *= sc; rb.z *= sc; rb.w *= sc;
            m = p;
            wgt = 1.f;
        } else {
            wgt = __expf(p - m);
        }
        s += wgt;
        ra.x += wgt * fa.x; ra.y += wgt * fa.y; ra.z += wgt * fa.z; ra.w += wgt * fa.w;
        rb.x += wgt * fb.x; rb.y += wgt * fb.y; rb.z += wgt * fb.z; rb.w += wgt * fb.w;
    }

    __shared__ float sm_m[8];
    __shared__ float sm_s[8];
    __shared__ float4 sm_ra[8][32];
    __shared__ float4 sm_rb[8][32];
    if (lane == 0) { sm_m[w] = m; sm_s[w] = s; }
    sm_ra[w][lane] = ra;
    sm_rb[w][lane] = rb;
    __syncthreads();

    int d = tid;
    float M = -CUDART_INF_F;
#pragma unroll
    for (int i = 0; i < 8; i++) { M = fmaxf(M, sm_m[i]); }

    float S = 0.f, R = 0.f;
    if (M > -CUDART_INF_F) {
        const float* base;
        if (d < 128) { base = ((const float*)sm_ra) + d; }
        else         { base = ((const float*)sm_rb) + (d - 128); }
#pragma unroll
        for (int i = 0; i < 8; i++) {
            float sc = __expf(sm_m[i] - M);
            S += sm_s[i] * sc;
            R += base[i * 128] * sc;
        }
    }
    g_pr[(size_t)u * D + d] = R;
    if (tid == 0) { g_pm[u] = M; g_ps[u] = S; }
}

// ---------------- iters 1..5: fp16 attention, 2-node + software prefetch ----------------
__global__ void __launch_bounds__(256)
attn_phase1_f16_kernel(int parity)
{
    int u = blockIdx.x;
    int b = u >> 2;
    int sp = u & 3;
    int tid = threadIdx.x;
    int w = tid >> 5;
    int lane = tid & 31;

    __shared__ float q_sm[D];
    lstm_elem(b, parity, q_sm);
    __syncthreads();

    int start = g_segoff[b];
    int end = g_segoff[b + 1];

    float qv[8];
#pragma unroll
    for (int i = 0; i < 8; i++) { qv[i] = q_sm[lane * 8 + i]; }

    float m = -CUDART_INF_F, s = 0.f;
    float r[8];
#pragma unroll
    for (int i = 0; i < 8; i++) { r[i] = 0.f; }

    int n = start + sp * 8 + w;

    // software-pipelined pair loop: loads for iteration k+1 issue before
    // iteration k's unpack/shuffle/exp chain consumes v0/v1.
    uint4 v0, v1;
    if (n + 32 < end) {
        v0 = ((const uint4*)(g_feat16 + (size_t)n * D))[lane];
        v1 = ((const uint4*)(g_feat16 + (size_t)(n + 32) * D))[lane];
    }
    while (n + 32 < end) {
        int nn = n + 64;
        uint4 w0 = v0, w1 = v1;
        if (nn + 32 < end) {
            w0 = ((const uint4*)(g_feat16 + (size_t)nn * D))[lane];
            w1 = ((const uint4*)(g_feat16 + (size_t)(nn + 32) * D))[lane];
        }

        float f0[8];
        float f1[8];
        unpack8(v0, f0);
        unpack8(v1, f1);

        float p0 = 0.f, p1 = 0.f;
#pragma unroll
        for (int i = 0; i < 8; i++) { p0 += f0[i] * qv[i]; p1 += f1[i] * qv[i]; }
#pragma unroll
        for (int o = 16; o; o >>= 1) {
            p0 += __shfl_xor_sync(0xffffffffu, p0, o);
            p1 += __shfl_xor_sync(0xffffffffu, p1, o);
        }

        float pmax = fmaxf(p0, p1);
        if (pmax > m) {
            float sc = __expf(m - pmax);   // first pair: exp(-inf) = +0
            s *= sc;
#pragma unroll
            for (int i = 0; i < 8; i++) { r[i] *= sc; }
            m = pmax;
        }
        float w0f = __expf(p0 - m);
        float w1f = __expf(p1 - m);
        s += w0f + w1f;
#pragma unroll
        for (int i = 0; i < 8; i++) { r[i] += w0f * f0[i] + w1f * f1[i]; }

        v0 = w0;
        v1 = w1;
        n = nn;
    }
    // tail: remaining single nodes
    for (; n < end; n += 32) {
        uint4 t0 = ((const uint4*)(g_feat16 + (size_t)n * D))[lane];
        float f0[8];
        unpack8(t0, f0);
        float p = 0.f;
#pragma unroll
        for (int i = 0; i < 8; i++) { p += f0[i] * qv[i]; }
#pragma unroll
        for (int o = 16; o; o >>= 1) { p += __shfl_xor_sync(0xffffffffu, p, o); }
        if (p > m) {
            float sc = __expf(m - p);
            s *= sc;
#pragma unroll
            for (int i = 0; i < 8; i++) { r[i] *= sc; }
            m = p;
        }
        float w0f = __expf(p - m);
        s += w0f;
#pragma unroll
        for (int i = 0; i < 8; i++) { r[i] += w0f * f0[i]; }
    }

    __shared__ float sm_m[8];
    __shared__ float sm_s[8];
    __shared__ float sm_r[8][D];
    if (lane == 0) { sm_m[w] = m; sm_s[w] = s; }
    *(float4*)&sm_r[w][lane * 8 + 0] = make_float4(r[0], r[1], r[2], r[3]);
    *(float4*)&sm_r[w][lane * 8 + 4] = make_float4(r[4], r[5], r[6], r[7]);
    __syncthreads();

    int d = tid;
    float M = -CUDART_INF_F;
#pragma unroll
    for (int i = 0; i < 8; i++) { M = fmaxf(M, sm_m[i]); }

    float S = 0.f, R = 0.f;
    if (M > -CUDART_INF_F) {
#pragma unroll
        for (int i = 0; i < 8; i++) {
            float sc = __expf(sm_m[i] - M);
            S += sm_s[i] * sc;
            R += sm_r[i][d] * sc;
        }
    }
    g_pr[(size_t)u * D + d] = R;
    if (tid == 0) { g_pm[u] = M; g_ps[u] = S; }
}

// ---------------- merge NSPLIT partials per graph ----------------
__global__ void __launch_bounds__(256)
attn_merge_kernel()
{
    int b = blockIdx.x;
    int d = threadIdx.x;

    float pm[NSPLIT];
#pragma unroll
    for (int i = 0; i < NSPLIT; i++) { pm[i] = g_pm[b * NSPLIT + i]; }

    float M = -CUDART_INF_F;
#pragma unroll
    for (int i = 0; i < NSPLIT; i++) { M = fmaxf(M, pm[i]); }

    float out = 0.f;
    if (M > -CUDART_INF_F) {
        float S = 0.f, R = 0.f;
#pragma unroll
        for (int i = 0; i < NSPLIT; i++) {
            float e = __expf(pm[i] - M);
            S += g_ps[b * NSPLIT + i] * e;
            R += g_pr[(size_t)(b * NSPLIT + i) * D + d] * e;
        }
        if (S > 0.f) { out = R / S; }
    }
    g_read[(size_t)b * D + d] = out;                          // fp32 (fc GEMM)
    g_x16[(size_t)b * 2 * D + D + d] = __float2half(out);     // fp16 (gates GEMM)
}

// ---------------- launch ----------------
extern "C" void kernel_launch(void* const* d_in, const int* in_sizes, int n_in,
                              void* d_out, int out_size)
{
    const float* feat = 0;
    const float* W_ih = 0;
    const float* W_hh = 0;
    const float* fc_w = 0;
    const float* fc_b = 0;
    const float* b_1 = 0;
    const float* b_2 = 0;
    const int* seg = 0;

    int fi = 0;
    long long best = -1;
    for (int i = 0; i < n_in; i++) {
        if ((long long)in_sizes[i] > best) { best = in_sizes[i]; fi = i; }
    }
    feat = (const float*)d_in[fi];
    int N = in_sizes[fi] / D;

    for (int i = 0; i < n_in; i++) {
        if (i == fi) continue;
        int s = in_sizes[i];
        if      (s == 4 * D * 2 * D) { W_ih = (const float*)d_in[i]; }
        else if (s == 4 * D * D)     { W_hh = (const float*)d_in[i]; }
        else if (s == D * 2 * D)     { fc_w = (const float*)d_in[i]; }
        else if (s == 4 * D)         { if (!b_1) { b_1 = (const float*)d_in[i]; }
                                       else      { b_2 = (const float*)d_in[i]; } }
        else if (s == D)             { fc_b = (const float*)d_in[i]; }
        else if (s == N)             { seg  = (const int*)d_in[i]; }
    }
    float* out = (float*)d_out;

    seg_offsets_kernel<<<(NGRAPH + 1 + 255) / 256, 256>>>(seg, N);
    prep_w16_kernel<<<(4 * D * 2 * D + 255) / 256, 256>>>(W_ih, W_hh);

    dim3 gGates(1024 / 128, 1024 / 64);   // (8, 16) = 128 blocks
    dim3 gFc(D / 64, NGRAPH / 64);        // (4, 16)

    for (int it = 0; it < NITERS; it++) {
        if (it == 0) {
            attn_phase1_f32_kernel<<<NGRAPH * NSPLIT, 256>>>(feat, b_1, b_2);
        } else {
            gemm_gates_mma_kernel<<<gGates, 256>>>(b_1, b_2);
            attn_phase1_f16_kernel<<<NGRAPH * NSPLIT, 256>>>(it & 1);
        }
        attn_merge_kernel<<<NGRAPH, 256>>>();
    }
    gemm_fc_kernel<<<gFc, 256>>>(fc_w, fc_b, out);
}

// round 17
// speedup vs baseline: 1.1125x; 1.0470x over previous
#include <cuda_runtime.h>
#include <cuda_fp16.h>
#include <math_constants.h>
#include <cstdint>

typedef unsigned int u32;

#define NGRAPH 1024
#define D      256
#define NITERS 6
#define NSPLIT 4
#define MAXN   400000

// ---------------- device scratch ----------------
__device__ __align__(16) float g_h[NGRAPH * D];
__device__ __align__(16) float g_read[NGRAPH * D];
__device__ __align__(16) float g_c[2][NGRAPH * D];            // ping-pong
__device__ __align__(16) float g_gates[NGRAPH * 4 * D];
__device__ __align__(16) __half g_x16[NGRAPH * 2 * D];        // [1024][512] = [h | read] fp16
__device__ __align__(16) __half g_W16[4 * D * 2 * D];         // [1024][512] = [Wc | Wr] fp16
__device__ __align__(16) float g_pm[NGRAPH * NSPLIT];
__device__ __align__(16) float g_ps[NGRAPH * NSPLIT];
__device__ __align__(16) float g_pr[NGRAPH * NSPLIT * D];
__device__ __align__(16) __half g_feat16[(size_t)MAXN * D];   // fp16 feat copy
__device__ int g_segoff[NGRAPH + 1];

// ---------------- helpers ----------------
__device__ __forceinline__ u32 smem_u32(const void* p) {
    return (u32)__cvta_generic_to_shared(p);
}

__device__ __forceinline__ void ldsm4(u32* r, u32 addr) {
    asm volatile("ldmatrix.sync.aligned.m8n8.x4.shared.b16 {%0,%1,%2,%3}, [%4];"
        : "=r"(r[0]), "=r"(r[1]), "=r"(r[2]), "=r"(r[3]) : "r"(addr));
}

__device__ __forceinline__ void mma16816(float* c, const u32* a, u32 b0, u32 b1) {
    asm volatile(
        "mma.sync.aligned.m16n8k16.row.col.f32.f16.f16.f32 "
        "{%0,%1,%2,%3}, {%4,%5,%6,%7}, {%8,%9}, {%0,%1,%2,%3};"
        : "+f"(c[0]), "+f"(c[1]), "+f"(c[2]), "+f"(c[3])
        : "r"(a[0]), "r"(a[1]), "r"(a[2]), "r"(a[3]), "r"(b0), "r"(b1));
}

__device__ __forceinline__ void cp_async16(u32 smem_addr, const void* gptr) {
    asm volatile("cp.async.cg.shared.global [%0], [%1], 16;"
        :: "r"(smem_addr), "l"(gptr));
}
__device__ __forceinline__ void cp_commit() {
    asm volatile("cp.async.commit_group;");
}
__device__ __forceinline__ void cp_wait1() {
    asm volatile("cp.async.wait_group 1;");
}

__device__ __forceinline__ void unpack8(uint4 v, float* f) {
    float2 t0 = __half22float2(*(__half2*)&v.x);
    float2 t1 = __half22float2(*(__half2*)&v.y);
    float2 t2 = __half22float2(*(__half2*)&v.z);
    float2 t3 = __half22float2(*(__half2*)&v.w);
    f[0] = t0.x; f[1] = t0.y; f[2] = t1.x; f[3] = t1.y;
    f[4] = t2.x; f[5] = t2.y; f[6] = t3.x; f[7] = t3.y;
}

// ---------------- segment offsets ----------------
__global__ void seg_offsets_kernel(const int* __restrict__ seg, int N) {
    int b = blockIdx.x * blockDim.x + threadIdx.x;
    if (b > NGRAPH) return;
    int lo = 0, hi = N;
    while (lo < hi) {
        int mid = (lo + hi) >> 1;
        if (seg[mid] < b) lo = mid + 1; else hi = mid;
    }
    g_segoff[b] = lo;
}

// W16[n][k] = W_ih[n][k] + (k < 256 ? W_hh[n][k] : 0), fp16
__global__ void prep_w16_kernel(const float* __restrict__ W_ih,
                                const float* __restrict__ W_hh) {
    int i = blockIdx.x * blockDim.x + threadIdx.x;
    if (i >= 4 * D * 2 * D) return;
    int n = i >> 9;
    int k = i & 511;
    float v = W_ih[(size_t)n * 2 * D + k];
    if (k < D) v += W_hh[(size_t)n * D + k];
    g_W16[i] = __float2half(v);
}

// ---------------- tensor-core gates GEMM, 3-stage cp.async pipeline ----------------
// gates[1024,1024] = X16[1024,512] @ W16[1024,512]^T + (b1 + b2)
// BM=64, BN=128, BK=32, 256 threads (8 warps: 2x4), grid (8,16) = 128 blocks.
__global__ void __launch_bounds__(256)
gemm_gates_mma_kernel(const float* __restrict__ b1, const float* __restrict__ b2)
{
    const int PAD = 40;     // halves per padded row (80B stride, conflict-free ldsm)
    __shared__ __half As[3][64][PAD];
    __shared__ __half Bs[3][128][PAD];

    int tid = threadIdx.x;
    int warp = tid >> 5;
    int lane = tid & 31;
    int wm = warp >> 2;       // 0..1
    int wn = warp & 3;        // 0..3
    int row0 = blockIdx.y * 64;
    int col0 = blockIdx.x * 128;

    float acc[2][4][4];
#pragma unroll
    for (int i = 0; i < 2; i++) {
#pragma unroll
        for (int j = 0; j < 4; j++) {
#pragma unroll
            for (int k = 0; k < 4; k++) { acc[i][j][k] = 0.f; }
        }
    }

    int arow = tid >> 2;
    int acol = (tid & 3) * 8;

    const __half* gA  = g_x16 + (size_t)(row0 + arow) * 512 + acol;
    const __half* gB0 = g_W16 + (size_t)(col0 + arow) * 512 + acol;
    const __half* gB1 = g_W16 + (size_t)(col0 + arow + 64) * 512 + acol;

    int a_r = lane & 15;
    int a_c = (lane >> 4) * 8;
    int b_rr = lane & 7;
    int b_sel = lane >> 3;
    int b_rowoff = (b_sel >> 1) * 8 + b_rr;
    int b_coloff = (b_sel & 1) * 8;

#define GATES_ISSUE(t_)                                                   \
    do {                                                                  \
        int buf_ = (t_) % 3;                                              \
        int kk_ = (t_) * 32;                                              \
        cp_async16(smem_u32(&As[buf_][arow][acol]), gA + kk_);            \
        cp_async16(smem_u32(&Bs[buf_][arow][acol]), gB0 + kk_);           \
        cp_async16(smem_u32(&Bs[buf_][arow + 64][acol]), gB1 + kk_);      \
        cp_commit();                                                      \
    } while (0)

    GATES_ISSUE(0);
    GATES_ISSUE(1);

    for (int t = 0; t < 16; t++) {
        cp_wait1();           // stage t landed (<=1 group pending: stage t+1)
        __syncthreads();
        int cur = t % 3;
#pragma unroll
        for (int ks = 0; ks < 2; ks++) {
            u32 afrag[2][4];
            u32 bfrag[2][4];
#pragma unroll
            for (int mt = 0; mt < 2; mt++) {
                u32 addr = smem_u32(&As[cur][wm * 32 + mt * 16 + a_r][ks * 16 + a_c]);
                ldsm4(afrag[mt], addr);
            }
#pragma unroll
            for (int g = 0; g < 2; g++) {
                u32 addr = smem_u32(&Bs[cur][wn * 32 + g * 16 + b_rowoff][ks * 16 + b_coloff]);
                ldsm4(bfrag[g], addr);
            }
#pragma unroll
            for (int mt = 0; mt < 2; mt++) {
#pragma unroll
                for (int g = 0; g < 2; g++) {
                    mma16816(acc[mt][g * 2 + 0], afrag[mt], bfrag[g][0], bfrag[g][1]);
                    mma16816(acc[mt][g * 2 + 1], afrag[mt], bfrag[g][2], bfrag[g][3]);
                }
            }
        }
        if (t + 2 < 16) { GATES_ISSUE(t + 2); }
    }
#undef GATES_ISSUE

    int trow = lane >> 2;
    int tcol = (lane & 3) * 2;
#pragma unroll
    for (int mt = 0; mt < 2; mt++) {
#pragma unroll
        for (int nt = 0; nt < 4; nt++) {
            int col = col0 + wn * 32 + nt * 8 + tcol;
            float bb0 = b1[col] + b2[col];
            float bb1 = b1[col + 1] + b2[col + 1];
            int r0 = row0 + wm * 32 + mt * 16 + trow;
            float2* p0 = (float2*)(g_gates + (size_t)r0 * 4 * D + col);
            float2* p1 = (float2*)(g_gates + (size_t)(r0 + 8) * 4 * D + col);
            *p0 = make_float2(acc[mt][nt][0] + bb0, acc[mt][nt][1] + bb1);
            *p1 = make_float2(acc[mt][nt][2] + bb0, acc[mt][nt][3] + bb1);
        }
    }
}

// ---------------- fp32 fc GEMM (runs once) ----------------
__global__ void __launch_bounds__(256)
gemm_fc_kernel(const float* __restrict__ fc_w, const float* __restrict__ fc_b,
               float* __restrict__ out)
{
    const int BK = 16, T = 32;
    __shared__ float As[2][BK][64];
    __shared__ float Bs[2][BK][64];

    int tid = threadIdx.x;
    int tx = tid & 15;
    int ty = tid >> 4;
    int row0 = blockIdx.y * 64;
    int col0 = blockIdx.x * 64;
    int lr = tid >> 2;
    int lc = (tid & 3) * 4;

    float acc[4][4];
#pragma unroll
    for (int i = 0; i < 4; i++) {
#pragma unroll
        for (int j = 0; j < 4; j++) { acc[i][j] = 0.f; }
    }

    float4 av, bv;
    av = *(const float4*)(g_h + (size_t)(row0 + lr) * D + lc);
    bv = *(const float4*)(fc_w + (size_t)(col0 + lr) * 2 * D + lc);
    As[0][lc + 0][lr] = av.x; As[0][lc + 1][lr] = av.y;
    As[0][lc + 2][lr] = av.z; As[0][lc + 3][lr] = av.w;
    Bs[0][lc + 0][lr] = bv.x; Bs[0][lc + 1][lr] = bv.y;
    Bs[0][lc + 2][lr] = bv.z; Bs[0][lc + 3][lr] = bv.w;
    __syncthreads();

    for (int t = 0; t < T; t++) {
        if (t + 1 < T) {
            int kk = (t + 1) * BK + lc;
            const float* A = (kk < D) ? g_h : g_read;
            int k2 = (kk < D) ? kk : kk - D;
            av = *(const float4*)(A + (size_t)(row0 + lr) * D + k2);
            bv = *(const float4*)(fc_w + (size_t)(col0 + lr) * 2 * D + kk);
        }
        int cur = t & 1;
#pragma unroll
        for (int k = 0; k < BK; k++) {
            float a[4], b[4];
#pragma unroll
            for (int i = 0; i < 4; i++) { a[i] = As[cur][k][ty * 4 + i]; }
#pragma unroll
            for (int j = 0; j < 4; j++) { b[j] = Bs[cur][k][tx * 4 + j]; }
#pragma unroll
            for (int i = 0; i < 4; i++) {
#pragma unroll
                for (int j = 0; j < 4; j++) { acc[i][j] += a[i] * b[j]; }
            }
        }
        if (t + 1 < T) {
            int nb = cur ^ 1;
            As[nb][lc + 0][lr] = av.x; As[nb][lc + 1][lr] = av.y;
            As[nb][lc + 2][lr] = av.z; As[nb][lc + 3][lr] = av.w;
            Bs[nb][lc + 0][lr] = bv.x; Bs[nb][lc + 1][lr] = bv.y;
            Bs[nb][lc + 2][lr] = bv.z; Bs[nb][lc + 3][lr] = bv.w;
        }
        __syncthreads();
    }

#pragma unroll
    for (int j = 0; j < 4; j++) {
        int col = col0 + tx * 4 + j;
        float bias = fc_b[col];
#pragma unroll
        for (int i = 0; i < 4; i++) {
            int row = row0 + ty * 4 + i;
            out[(size_t)row * D + col] = acc[i][j] + bias;
        }
    }
}

// ---------------- LSTM-elementwise helpers ----------------
__device__ __forceinline__ void lstm_elem(int b, int parity, float* q_sm) {
    const float* g = g_gates + (size_t)b * 4 * D;
    int d = threadIdx.x;
    float gi = g[d];
    float gf = g[D + d];
    float gg = g[2 * D + d];
    float go = g[3 * D + d];
    float si = 1.f / (1.f + __expf(-gi));
    float so = 1.f / (1.f + __expf(-go));
    float sf = 1.f / (1.f + __expf(-gf));
    float c = sf * g_c[parity][(size_t)b * D + d] + si * tanhf(gg);
    float h = so * tanhf(c);
    g_c[parity ^ 1][(size_t)b * D + d] = c;
    g_h[(size_t)b * D + d] = h;                       // fp32 (fc GEMM)
    g_x16[(size_t)b * 2 * D + d] = __float2half(h);   // fp16 (gates GEMM)
    q_sm[d] = h;
}

// Iter-0 path: gates = b1 + b2 (all GEMM inputs are zero), c_prev = 0.
__device__ __forceinline__ void lstm_elem_bias(int b, const float* b1,
                                               const float* b2, float* q_sm) {
    int d = threadIdx.x;
    float gi = b1[d] + b2[d];
    float gg = b1[2 * D + d] + b2[2 * D + d];
    float go = b1[3 * D + d] + b2[3 * D + d];
    float si = 1.f / (1.f + __expf(-gi));
    float so = 1.f / (1.f + __expf(-go));
    float c = si * tanhf(gg);                         // sf * 0 + si*tanh(g)
    float h = so * tanhf(c);
    g_c[1][(size_t)b * D + d] = c;                    // iter 0 writes parity 0^1 = 1
    g_h[(size_t)b * D + d] = h;
    g_x16[(size_t)b * 2 * D + d] = __float2half(h);
    q_sm[d] = h;
}

// ---------------- iter-0: fp32 attention + fp16 conversion write ----------------
__global__ void __launch_bounds__(256)
attn_phase1_f32_kernel(const float* __restrict__ feat,
                       const float* __restrict__ b1, const float* __restrict__ b2)
{
    int u = blockIdx.x;
    int b = u >> 2;
    int sp = u & 3;
    int tid = threadIdx.x;
    int w = tid >> 5;
    int lane = tid & 31;

    __shared__ float q_sm[D];
    lstm_elem_bias(b, b1, b2, q_sm);
    __syncthreads();

    int start = g_segoff[b];
    int end = g_segoff[b + 1];

    float4 qa = *(const float4*)(q_sm + lane * 4);
    float4 qb = *(const float4*)(q_sm + 128 + lane * 4);

    float m = -CUDART_INF_F, s = 0.f;
    float4 ra = make_float4(0.f, 0.f, 0.f, 0.f);
    float4 rb = make_float4(0.f, 0.f, 0.f, 0.f);

    for (int n = start + sp * 8 + w; n < end; n += 32) {
        const float4* fp = (const float4*)(feat + (size_t)n * D);
        float4 fa = fp[lane];
        float4 fb = fp[32 + lane];

        __half* row16 = g_feat16 + (size_t)n * D;
        ((__half2*)row16)[lane * 2 + 0] = __float22half2_rn(make_float2(fa.x, fa.y));
        ((__half2*)row16)[lane * 2 + 1] = __float22half2_rn(make_float2(fa.z, fa.w));
        ((__half2*)(row16 + 128))[lane * 2 + 0] = __float22half2_rn(make_float2(fb.x, fb.y));
        ((__half2*)(row16 + 128))[lane * 2 + 1] = __float22half2_rn(make_float2(fb.z, fb.w));

        float p = fa.x * qa.x + fa.y * qa.y + fa.z * qa.z + fa.w * qa.w
                + fb.x * qb.x + fb.y * qb.y + fb.z * qb.z + fb.w * qb.w;
#pragma unroll
        for (int o = 16; o; o >>= 1) { p += __shfl_xor_sync(0xffffffffu, p, o); }

        float wgt;
        if (p > m) {
            float sc = __expf(m - p);   // first node: exp(-inf) = +0
            s *= sc;
            ra.x *= sc; ra.y *= sc; ra.z *= sc; ra.w *= sc;
            rb.x *= sc; rb.y *= sc; rb.z *= sc; rb.w *= sc;
            m = p;
            wgt = 1.f;
        } else {
            wgt = __expf(p - m);
        }
        s += wgt;
        ra.x += wgt * fa.x; ra.y += wgt * fa.y; ra.z += wgt * fa.z; ra.w += wgt * fa.w;
        rb.x += wgt * fb.x; rb.y += wgt * fb.y; rb.z += wgt * fb.z; rb.w += wgt * fb.w;
    }

    __shared__ float sm_m[8];
    __shared__ float sm_s[8];
    __shared__ float4 sm_ra[8][32];
    __shared__ float4 sm_rb[8][32];
    if (lane == 0) { sm_m[w] = m; sm_s[w] = s; }
    sm_ra[w][lane] = ra;
    sm_rb[w][lane] = rb;
    __syncthreads();

    int d = tid;
    float M = -CUDART_INF_F;
#pragma unroll
    for (int i = 0; i < 8; i++) { M = fmaxf(M, sm_m[i]); }

    float S = 0.f, R = 0.f;
    if (M > -CUDART_INF_F) {
        const float* base;
        if (d < 128) { base = ((const float*)sm_ra) + d; }
        else         { base = ((const float*)sm_rb) + (d - 128); }
#pragma unroll
        for (int i = 0; i < 8; i++) {
            float sc = __expf(sm_m[i] - M);
            S += sm_s[i] * sc;
            R += base[i * 128] * sc;
        }
    }
    g_pr[(size_t)u * D + d] = R;
    if (tid == 0) { g_pm[u] = M; g_ps[u] = S; }
}

// ---------------- iters 1..5: fp16 attention, 2-node unroll ----------------
__global__ void __launch_bounds__(256)
attn_phase1_f16_kernel(int parity)
{
    int u = blockIdx.x;
    int b = u >> 2;
    int sp = u & 3;
    int tid = threadIdx.x;
    int w = tid >> 5;
    int lane = tid & 31;

    __shared__ float q_sm[D];
    lstm_elem(b, parity, q_sm);
    __syncthreads();

    int start = g_segoff[b];
    int end = g_segoff[b + 1];

    float qv[8];
#pragma unroll
    for (int i = 0; i < 8; i++) { qv[i] = q_sm[lane * 8 + i]; }

    float m = -CUDART_INF_F, s = 0.f;
    float r[8];
#pragma unroll
    for (int i = 0; i < 8; i++) { r[i] = 0.f; }

    int n = start + sp * 8 + w;
    for (; n + 32 < end; n += 64) {
        uint4 v0 = ((const uint4*)(g_feat16 + (size_t)n * D))[lane];
        uint4 v1 = ((const uint4*)(g_feat16 + (size_t)(n + 32) * D))[lane];
        float f0[8];
        float f1[8];
        unpack8(v0, f0);
        unpack8(v1, f1);

        float p0 = 0.f, p1 = 0.f;
#pragma unroll
        for (int i = 0; i < 8; i++) { p0 += f0[i] * qv[i]; p1 += f1[i] * qv[i]; }
#pragma unroll
        for (int o = 16; o; o >>= 1) {
            p0 += __shfl_xor_sync(0xffffffffu, p0, o);
            p1 += __shfl_xor_sync(0xffffffffu, p1, o);
        }

        float pmax = fmaxf(p0, p1);
        if (pmax > m) {
            float sc = __expf(m - pmax);   // first pair: exp(-inf) = +0
            s *= sc;
#pragma unroll
            for (int i = 0; i < 8; i++) { r[i] *= sc; }
            m = pmax;
        }
        float w0 = __expf(p0 - m);
        float w1 = __expf(p1 - m);
        s += w0 + w1;
#pragma unroll
        for (int i = 0; i < 8; i++) { r[i] += w0 * f0[i] + w1 * f1[i]; }
    }
    if (n < end) {
        uint4 v0 = ((const uint4*)(g_feat16 + (size_t)n * D))[lane];
        float f0[8];
        unpack8(v0, f0);
        float p = 0.f;
#pragma unroll
        for (int i = 0; i < 8; i++) { p += f0[i] * qv[i]; }
#pragma unroll
        for (int o = 16; o; o >>= 1) { p += __shfl_xor_sync(0xffffffffu, p, o); }
        if (p > m) {
            float sc = __expf(m - p);
            s *= sc;
#pragma unroll
            for (int i = 0; i < 8; i++) { r[i] *= sc; }
            m = p;
        }
        float w0 = __expf(p - m);
        s += w0;
#pragma unroll
        for (int i = 0; i < 8; i++) { r[i] += w0 * f0[i]; }
    }

    __shared__ float sm_m[8];
    __shared__ float sm_s[8];
    __shared__ float sm_r[8][D];
    if (lane == 0) { sm_m[w] = m; sm_s[w] = s; }
    *(float4*)&sm_r[w][lane * 8 + 0] = make_float4(r[0], r[1], r[2], r[3]);
    *(float4*)&sm_r[w][lane * 8 + 4] = make_float4(r[4], r[5], r[6], r[7]);
    __syncthreads();

    int d = tid;
    float M = -CUDART_INF_F;
#pragma unroll
    for (int i = 0; i < 8; i++) { M = fmaxf(M, sm_m[i]); }

    float S = 0.f, R = 0.f;
    if (M > -CUDART_INF_F) {
#pragma unroll
        for (int i = 0; i < 8; i++) {
            float sc = __expf(sm_m[i] - M);
            S += sm_s[i] * sc;
            R += sm_r[i][d] * sc;
        }
    }
    g_pr[(size_t)u * D + d] = R;
    if (tid == 0) { g_pm[u] = M; g_ps[u] = S; }
}

// ---------------- merge NSPLIT partials per graph ----------------
__global__ void __launch_bounds__(256)
attn_merge_kernel()
{
    int b = blockIdx.x;
    int d = threadIdx.x;

    float pm[NSPLIT];
#pragma unroll
    for (int i = 0; i < NSPLIT; i++) { pm[i] = g_pm[b * NSPLIT + i]; }

    float M = -CUDART_INF_F;
#pragma unroll
    for (int i = 0; i < NSPLIT; i++) { M = fmaxf(M, pm[i]); }

    float out = 0.f;
    if (M > -CUDART_INF_F) {
        float S = 0.f, R = 0.f;
#pragma unroll
        for (int i = 0; i < NSPLIT; i++) {
            float e = __expf(pm[i] - M);
            S += g_ps[b * NSPLIT + i] * e;
            R += g_pr[(size_t)(b * NSPLIT + i) * D + d] * e;
        }
        if (S > 0.f) { out = R / S; }
    }
    g_read[(size_t)b * D + d] = out;                          // fp32 (fc GEMM)
    g_x16[(size_t)b * 2 * D + D + d] = __float2half(out);     // fp16 (gates GEMM)
}

// ---------------- launch ----------------
extern "C" void kernel_launch(void* const* d_in, const int* in_sizes, int n_in,
                              void* d_out, int out_size)
{
    const float* feat = 0;
    const float* W_ih = 0;
    const float* W_hh = 0;
    const float* fc_w = 0;
    const float* fc_b = 0;
    const float* b_1 = 0;
    const float* b_2 = 0;
    const int* seg = 0;

    int fi = 0;
    long long best = -1;
    for (int i = 0; i < n_in; i++) {
        if ((long long)in_sizes[i] > best) { best = in_sizes[i]; fi = i; }
    }
    feat = (const float*)d_in[fi];
    int N = in_sizes[fi] / D;

    for (int i = 0; i < n_in; i++) {
        if (i == fi) continue;
        int s = in_sizes[i];
        if      (s == 4 * D * 2 * D) { W_ih = (const float*)d_in[i]; }
        else if (s == 4 * D * D)     { W_hh = (const float*)d_in[i]; }
        else if (s == D * 2 * D)     { fc_w = (const float*)d_in[i]; }
        else if (s == 4 * D)         { if (!b_1) { b_1 = (const float*)d_in[i]; }
                                       else      { b_2 = (const float*)d_in[i]; } }
        else if (s == D)             { fc_b = (const float*)d_in[i]; }
        else if (s == N)             { seg  = (const int*)d_in[i]; }
    }
    float* out = (float*)d_out;

    seg_offsets_kernel<<<(NGRAPH + 1 + 255) / 256, 256>>>(seg, N);
    prep_w16_kernel<<<(4 * D * 2 * D + 255) / 256, 256>>>(W_ih, W_hh);

    dim3 gGates(1024 / 128, 1024 / 64);   // (8, 16) = 128 blocks
    dim3 gFc(D / 64, NGRAPH / 64);        // (4, 16)

    for (int it = 0; it < NITERS; it++) {
        if (it == 0) {
            attn_phase1_f32_kernel<<<NGRAPH * NSPLIT, 256>>>(feat, b_1, b_2);
        } else {
            gemm_gates_mma_kernel<<<gGates, 256>>>(b_1, b_2);
            attn_phase1_f16_kernel<<<NGRAPH * NSPLIT, 256>>>(it & 1);
        }
        attn_merge_kernel<<<NGRAPH, 256>>>();
    }
    gemm_fc_kernel<<<gFc, 256>>>(fc_w, fc_b, out);
}